// round 1
// baseline (speedup 1.0000x reference)
#include <cuda_runtime.h>
#include <cstdint>
#include <cstddef>

// Problem constants
#define B_      64
#define T_      1024
#define F_      256
#define U_      512
#define G3_     1536
#define SIG_    31

// Persistent kernel config
#define GRID_   128          // CTAs; each owns 4 units
#define THREADS_ 256
#define KTOT_   768          // K = 256 (x) + 512 (h)
#define KC_     128          // K-chunk staged in smem
#define NCH_    6            // chunks per step (2 x, 4 h)
#define NCOL_   12           // 3 gates x 4 units per CTA
#define KS_     16           // K-split factor across threads

// Scratch (static __device__ arrays: no allocation)
__device__ float        g_f_all[(size_t)T_ * U_ * B_];   // sigmoid(f_pre), [t][u][b]
__device__ float        g_h[2][U_ * B_];                 // ping-pong h, [k=u][b] transposed
__device__ unsigned int g_bar;

__device__ __forceinline__ void fma2(unsigned long long& a, unsigned long long x,
                                     unsigned long long w) {
    asm("fma.rn.f32x2 %0, %1, %2, %0;" : "+l"(a) : "l"(x), "l"(w));
}
__device__ __forceinline__ float2 up2(unsigned long long v) {
    float2 r; asm("mov.b64 {%0, %1}, %2;" : "=f"(r.x), "=f"(r.y) : "l"(v)); return r;
}
__device__ __forceinline__ float sigmoidf_(float x) { return 1.f / (1.f + expf(-x)); }

// Zero the barrier counter + initial h (needed every launch: graph replays)
__global__ void reset_kernel() {
    int i = blockIdx.x * blockDim.x + threadIdx.x;
    if (i == 0) g_bar = 0u;
    if (i < U_ * B_) g_h[0][i] = 0.f;
}

// f_all[t][u][b] = sigmoid(signatures[b,t,:] . forget_kernel[:,u] + bias_f[u])
__global__ void fpre_kernel(const float* __restrict__ sig, const float* __restrict__ fk,
                            const float* __restrict__ bias) {
    __shared__ float sig_s[B_][33];  // pad to 33 to kill bank conflicts
    int t = blockIdx.x;
    for (int i = threadIdx.x; i < B_ * SIG_; i += THREADS_) {
        int b = i / SIG_, d = i - b * SIG_;
        sig_s[b][d] = sig[((size_t)b * T_ + t) * SIG_ + d];
    }
    __syncthreads();
    size_t base = (size_t)t * (U_ * B_);
    for (int idx = threadIdx.x; idx < U_ * B_; idx += THREADS_) {
        int u = idx >> 6, b = idx & 63;
        float acc = bias[U_ + u];
        #pragma unroll
        for (int d = 0; d < SIG_; d++) acc += sig_s[b][d] * __ldg(&fk[d * U_ + u]);
        g_f_all[base + idx] = 1.f / (1.f + expf(-acc));
    }
}

// Persistent recurrence. One CTA per 4 units; weights resident in SMEM (value-
// duplicated pairs for f32x2 FMA); c-state in registers; h exchanged via L2 +
// counter grid-barrier; x chunks transposed into SMEM on the fly each step.
__global__ void __launch_bounds__(THREADS_, 1)
lstm_kernel(const float* __restrict__ inputs, const float* __restrict__ ik,
            const float* __restrict__ rk, const float* __restrict__ bias,
            float* __restrict__ out) {
    extern __shared__ float smem[];
    float* w2 = smem;                        // [768][12][2] dup-pair weights  (73728 B)
    float* st = smem + KTOT_ * NCOL_ * 2;    // [2][128][64] stage buffers     (65536 B)
    float* rs = st + 2 * KC_ * B_;           // [16][12][64] K-split partials  (49152 B)

    const int tid  = threadIdx.x;
    const int ublk = blockIdx.x * 4;         // first unit owned by this CTA

    // Load weights once: rows 0..255 = input_kernel, 256..767 = recurrent_kernel.
    // col(j): gate g=j>>2 in {i,c,o}, unit uu=j&3 -> global col g*512 + ublk + uu
    for (int idx = tid; idx < KTOT_ * NCOL_; idx += THREADS_) {
        int k = idx / NCOL_, j = idx - k * NCOL_;
        int col = (j >> 2) * U_ + ublk + (j & 3);
        float w = (k < F_) ? ik[(size_t)k * G3_ + col]
                           : rk[(size_t)(k - F_) * G3_ + col];
        w2[idx * 2] = w; w2[idx * 2 + 1] = w;
    }

    // GEMM role: 16 batch-groups (4 batches each, as 2 f32x2 pairs) x 16 K-splits
    const int ks = tid >> 4, b4 = tid & 15;
    // Finalize role: one (batch, unit) pair per thread
    const int fb = tid & 63, fu = tid >> 6;
    const int u_g = ublk + fu;
    const float bi = bias[u_g], bc = bias[2 * U_ + u_g], bo = bias[3 * U_ + u_g];
    // x transpose-loader role
    const int lane = tid & 31, wrp = tid >> 5;
    const int xb  = (wrp & 1) * 32 + lane;
    const int xfq = wrp >> 1;
    const float* xsrc_base = inputs + (size_t)xb * T_ * F_ + xfq * 32;

    float c_state = 0.f;
    __syncthreads();

    // Prefetch x chunk 0 of t=0 into buffer 0 (transpose [b][f] -> st[f][b])
    {
        const float* src = xsrc_base;
        #pragma unroll
        for (int j4 = 0; j4 < 8; j4++) {
            float4 v = *(const float4*)(src + j4 * 4);
            int kl = xfq * 32 + j4 * 4;
            st[(kl + 0) * B_ + xb] = v.x; st[(kl + 1) * B_ + xb] = v.y;
            st[(kl + 2) * B_ + xb] = v.z; st[(kl + 3) * B_ + xb] = v.w;
        }
    }
    float fval = __ldcg(&g_f_all[(size_t)0 + u_g * B_ + fb]);

    for (int t = 0; t < T_; t++) {
        unsigned long long acc[NCOL_][2];
        #pragma unroll
        for (int j = 0; j < NCOL_; j++) { acc[j][0] = 0ull; acc[j][1] = 0ull; }

        #pragma unroll
        for (int c = 0; c < NCH_; c++) {
            __syncthreads();   // stage buffer (c&1) is ready
            if (c == 0) {
                // load x chunk 1 -> buffer 1 (transpose path)
                const float* src = xsrc_base + (size_t)t * F_ + KC_;
                float* d = st + KC_ * B_;
                #pragma unroll
                for (int j4 = 0; j4 < 8; j4++) {
                    float4 v = *(const float4*)(src + j4 * 4);
                    int kl = xfq * 32 + j4 * 4;
                    d[(kl + 0) * B_ + xb] = v.x; d[(kl + 1) * B_ + xb] = v.y;
                    d[(kl + 2) * B_ + xb] = v.z; d[(kl + 3) * B_ + xb] = v.w;
                }
            } else if (c < 5) {
                // load h chunk (c+1): rows (c-1)*128.. ; L2-coherent (bypass L1)
                const float4* src = (const float4*)(g_h[t & 1] + (c - 1) * KC_ * B_);
                float4* d4 = (float4*)(st + ((c + 1) & 1) * KC_ * B_);
                #pragma unroll
                for (int r = 0; r < 8; r++)
                    d4[r * THREADS_ + tid] = __ldcg(src + r * THREADS_ + tid);
            }
            // consume chunk c from buffer (c&1): 8 k-values per thread
            const float* buf = st + (c & 1) * KC_ * B_;
            const float* wb  = w2 + (size_t)c * KC_ * NCOL_ * 2;
            #pragma unroll
            for (int j = 0; j < 8; j++) {
                int k = ks * 8 + j;
                ulonglong2 hv = *(const ulonglong2*)(buf + k * B_ + b4 * 4);
                const ulonglong2* wr = (const ulonglong2*)(wb + k * NCOL_ * 2);
                #pragma unroll
                for (int j2 = 0; j2 < 6; j2++) {
                    ulonglong2 wv = wr[j2];
                    fma2(acc[2 * j2    ][0], hv.x, wv.x);
                    fma2(acc[2 * j2    ][1], hv.y, wv.x);
                    fma2(acc[2 * j2 + 1][0], hv.x, wv.y);
                    fma2(acc[2 * j2 + 1][1], hv.y, wv.y);
                }
            }
        }

        // K-split reduction: store partials, then gate-finalize per (b, unit)
        #pragma unroll
        for (int j = 0; j < NCOL_; j++) {
            *(float2*)&rs[(ks * NCOL_ + j) * B_ + b4 * 4    ] = up2(acc[j][0]);
            *(float2*)&rs[(ks * NCOL_ + j) * B_ + b4 * 4 + 2] = up2(acc[j][1]);
        }
        __syncthreads();

        float si = 0.f, sc = 0.f, so = 0.f;
        #pragma unroll
        for (int p = 0; p < KS_; p++) {
            si += rs[(p * NCOL_     + fu) * B_ + fb];
            sc += rs[(p * NCOL_ + 4 + fu) * B_ + fb];
            so += rs[(p * NCOL_ + 8 + fu) * B_ + fb];
        }
        float ig = sigmoidf_(si + bi);
        float cg = tanhf(sc + bc);
        float og = sigmoidf_(so + bo);
        c_state = fval * c_state + ig * cg;
        float h = og * tanhf(c_state);
        g_h[(t + 1) & 1][u_g * B_ + fb] = h;
        if (t == T_ - 1) out[fb * U_ + u_g] = h;

        // Prefetch barrier-independent data for t+1 BEFORE the grid barrier:
        // x chunk 0 (inputs only) + next f value.
        if (t < T_ - 1) {
            const float* src = xsrc_base + (size_t)(t + 1) * F_;
            #pragma unroll
            for (int j4 = 0; j4 < 8; j4++) {
                float4 v = *(const float4*)(src + j4 * 4);
                int kl = xfq * 32 + j4 * 4;
                st[(kl + 0) * B_ + xb] = v.x; st[(kl + 1) * B_ + xb] = v.y;
                st[(kl + 2) * B_ + xb] = v.z; st[(kl + 3) * B_ + xb] = v.w;
            }
            fval = __ldcg(&g_f_all[(size_t)(t + 1) * (U_ * B_) + u_g * B_ + fb]);
        }

        // Grid barrier: monotonic counter, one arrival per CTA per step.
        __threadfence();
        __syncthreads();
        if (tid == 0) {
            atomicAdd(&g_bar, 1u);
            unsigned tgt = (unsigned)(t + 1) * GRID_;
            volatile unsigned* p = &g_bar;
            while (*p < tgt) { }
        }
        __syncthreads();
    }
}

extern "C" void kernel_launch(void* const* d_in, const int* in_sizes, int n_in,
                              void* d_out, int out_size) {
    const float* inputs = (const float*)d_in[0];  // [64,1024,256]
    const float* sig    = (const float*)d_in[1];  // [64,1024,31]
    const float* fk     = (const float*)d_in[2];  // [31,512]
    const float* ik     = (const float*)d_in[3];  // [256,1536]
    const float* rk     = (const float*)d_in[4];  // [512,1536]
    const float* bias   = (const float*)d_in[5];  // [2048]
    float* out = (float*)d_out;                   // [64,512]
    (void)in_sizes; (void)n_in; (void)out_size;

    const int smem_bytes = (KTOT_ * NCOL_ * 2 + 2 * KC_ * B_ + KS_ * NCOL_ * B_) * 4;
    cudaFuncSetAttribute(lstm_kernel, cudaFuncAttributeMaxDynamicSharedMemorySize,
                         smem_bytes);

    reset_kernel<<<GRID_, THREADS_>>>();
    fpre_kernel<<<T_, THREADS_>>>(sig, fk, bias);
    lstm_kernel<<<GRID_, THREADS_, smem_bytes>>>(inputs, ik, rk, bias, out);
}

// round 2
// speedup vs baseline: 1.0251x; 1.0251x over previous
#include <cuda_runtime.h>
#include <cstdint>
#include <cstddef>

// Problem constants
#define B_      64
#define T_      1024
#define F_      256
#define U_      512
#define G3_     1536
#define SIG_    31

// Persistent kernel config
#define GRID_   128          // CTAs; each owns 4 units
#define THREADS_ 256
#define KTOT_   768          // K = 256 (x) + 512 (h)
#define KC_     128          // K-chunk staged in smem
#define NCH_    6            // chunks per step (2 x, 4 h)
#define NCOL_   12           // 3 gates x 4 units per CTA
#define KS_     16           // K-split factor across threads

// Scratch (static __device__ arrays: no allocation)
__device__ float        g_f_all[(size_t)T_ * U_ * B_];   // sigmoid(f_pre), [t][u][b]
__device__ float        g_h[2][U_ * B_];                 // ping-pong h, [k=u][b] transposed
__device__ unsigned int g_bar;

__device__ __forceinline__ void fma2(unsigned long long& a, unsigned long long x,
                                     unsigned long long w) {
    asm("fma.rn.f32x2 %0, %1, %2, %0;" : "+l"(a) : "l"(x), "l"(w));
}
__device__ __forceinline__ float2 up2(unsigned long long v) {
    float2 r; asm("mov.b64 {%0, %1}, %2;" : "=f"(r.x), "=f"(r.y) : "l"(v)); return r;
}
__device__ __forceinline__ float tanh_fast(float x) {
    float y; asm("tanh.approx.f32 %0, %1;" : "=f"(y) : "f"(x)); return y;
}
__device__ __forceinline__ float sigmoid_fast(float x) {
    return 1.f / (1.f + __expf(-x));
}

// f_all[t][u][b] = sigmoid(signatures[b,t,:] . forget_kernel[:,u] + bias_f[u])
// Also resets barrier counter + initial h (block 0..127) each launch (graph replays).
__global__ void fpre_kernel(const float* __restrict__ sig, const float* __restrict__ fk,
                            const float* __restrict__ bias) {
    __shared__ float sig_s[B_][33];  // pad to 33 to kill bank conflicts
    int t = blockIdx.x;
    if (t == 0 && threadIdx.x == 0) g_bar = 0u;
    if (t < GRID_) g_h[0][t * THREADS_ + threadIdx.x] = 0.f;
    for (int i = threadIdx.x; i < B_ * SIG_; i += THREADS_) {
        int b = i / SIG_, d = i - b * SIG_;
        sig_s[b][d] = sig[((size_t)b * T_ + t) * SIG_ + d];
    }
    __syncthreads();
    size_t base = (size_t)t * (U_ * B_);
    for (int idx = threadIdx.x; idx < U_ * B_; idx += THREADS_) {
        int u = idx >> 6, b = idx & 63;
        float acc = bias[U_ + u];
        #pragma unroll
        for (int d = 0; d < SIG_; d++) acc += sig_s[b][d] * __ldg(&fk[d * U_ + u]);
        g_f_all[base + idx] = 1.f / (1.f + expf(-acc));
    }
}

// Persistent recurrence. One CTA per 4 units; weights resident in SMEM (value-
// duplicated pairs for f32x2 FMA); c-state in registers; h exchanged via L2 +
// counter grid-barrier (release/acquire, early-arrive) ; x chunks transposed
// into SMEM on the fly each step.
__global__ void __launch_bounds__(THREADS_, 1)
lstm_kernel(const float* __restrict__ inputs, const float* __restrict__ ik,
            const float* __restrict__ rk, const float* __restrict__ bias,
            float* __restrict__ out) {
    extern __shared__ float smem[];
    float* w2 = smem;                        // [768][12][2] dup-pair weights  (73728 B)
    float* st = smem + KTOT_ * NCOL_ * 2;    // [2][128][64] stage buffers     (65536 B)
    float* rs = st + 2 * KC_ * B_;           // [16][12][64] K-split partials  (49152 B)

    const int tid  = threadIdx.x;
    const int ublk = blockIdx.x * 4;         // first unit owned by this CTA

    // Load weights once: rows 0..255 = input_kernel, 256..767 = recurrent_kernel.
    // col(j): gate g=j>>2 in {i,c,o}, unit uu=j&3 -> global col g*512 + ublk + uu
    for (int idx = tid; idx < KTOT_ * NCOL_; idx += THREADS_) {
        int k = idx / NCOL_, j = idx - k * NCOL_;
        int col = (j >> 2) * U_ + ublk + (j & 3);
        float w = (k < F_) ? ik[(size_t)k * G3_ + col]
                           : rk[(size_t)(k - F_) * G3_ + col];
        w2[idx * 2] = w; w2[idx * 2 + 1] = w;
    }

    // GEMM role: 16 batch-groups (4 batches each, as 2 f32x2 pairs) x 16 K-splits
    const int ks = tid >> 4, b4 = tid & 15;
    // Finalize role: one (batch, unit) pair per thread
    const int fb = tid & 63, fu = tid >> 6;
    const int u_g = ublk + fu;
    const float bi = bias[u_g], bc = bias[2 * U_ + u_g], bo = bias[3 * U_ + u_g];
    // x transpose-loader role
    const int lane = tid & 31, wrp = tid >> 5;
    const int xb  = (wrp & 1) * 32 + lane;
    const int xfq = wrp >> 1;
    const float* xsrc_base = inputs + (size_t)xb * T_ * F_ + xfq * 32;

    float c_state = 0.f;
    __syncthreads();

    // Prefetch x chunk 0 of t=0 into buffer 0 (transpose [b][f] -> st[f][b])
    {
        const float* src = xsrc_base;
        #pragma unroll
        for (int j4 = 0; j4 < 8; j4++) {
            float4 v = *(const float4*)(src + j4 * 4);
            int kl = xfq * 32 + j4 * 4;
            st[(kl + 0) * B_ + xb] = v.x; st[(kl + 1) * B_ + xb] = v.y;
            st[(kl + 2) * B_ + xb] = v.z; st[(kl + 3) * B_ + xb] = v.w;
        }
    }
    float fval = __ldcg(&g_f_all[(size_t)0 + u_g * B_ + fb]);

    for (int t = 0; t < T_; t++) {
        unsigned long long acc[NCOL_][2];
        #pragma unroll
        for (int j = 0; j < NCOL_; j++) { acc[j][0] = 0ull; acc[j][1] = 0ull; }

        #pragma unroll
        for (int c = 0; c < NCH_; c++) {
            __syncthreads();   // stage buffer (c&1) is ready
            if (c == 0) {
                // load x chunk 1 -> buffer 1 (transpose path)
                const float* src = xsrc_base + (size_t)t * F_ + KC_;
                float* d = st + KC_ * B_;
                #pragma unroll
                for (int j4 = 0; j4 < 8; j4++) {
                    float4 v = *(const float4*)(src + j4 * 4);
                    int kl = xfq * 32 + j4 * 4;
                    d[(kl + 0) * B_ + xb] = v.x; d[(kl + 1) * B_ + xb] = v.y;
                    d[(kl + 2) * B_ + xb] = v.z; d[(kl + 3) * B_ + xb] = v.w;
                }
            } else if (c < 5) {
                // load h chunk (c+1): rows (c-1)*128.. ; L2-coherent (bypass L1)
                const float4* src = (const float4*)(g_h[t & 1] + (c - 1) * KC_ * B_);
                float4* d4 = (float4*)(st + ((c + 1) & 1) * KC_ * B_);
                #pragma unroll
                for (int r = 0; r < 8; r++)
                    d4[r * THREADS_ + tid] = __ldcg(src + r * THREADS_ + tid);
            }
            // consume chunk c from buffer (c&1): 8 k-values per thread
            const float* buf = st + (c & 1) * KC_ * B_;
            const float* wb  = w2 + (size_t)c * KC_ * NCOL_ * 2;
            #pragma unroll
            for (int j = 0; j < 8; j++) {
                int k = ks * 8 + j;
                ulonglong2 hv = *(const ulonglong2*)(buf + k * B_ + b4 * 4);
                const ulonglong2* wr = (const ulonglong2*)(wb + k * NCOL_ * 2);
                #pragma unroll
                for (int j2 = 0; j2 < 6; j2++) {
                    ulonglong2 wv = wr[j2];
                    fma2(acc[2 * j2    ][0], hv.x, wv.x);
                    fma2(acc[2 * j2    ][1], hv.y, wv.x);
                    fma2(acc[2 * j2 + 1][0], hv.x, wv.y);
                    fma2(acc[2 * j2 + 1][1], hv.y, wv.y);
                }
            }
        }

        // K-split reduction: store partials, then gate-finalize per (b, unit)
        #pragma unroll
        for (int j = 0; j < NCOL_; j++) {
            *(float2*)&rs[(ks * NCOL_ + j) * B_ + b4 * 4    ] = up2(acc[j][0]);
            *(float2*)&rs[(ks * NCOL_ + j) * B_ + b4 * 4 + 2] = up2(acc[j][1]);
        }
        __syncthreads();

        float si = 0.f, sc = 0.f, so = 0.f;
        #pragma unroll
        for (int p = 0; p < KS_; p++) {
            si += rs[(p * NCOL_     + fu) * B_ + fb];
            sc += rs[(p * NCOL_ + 4 + fu) * B_ + fb];
            so += rs[(p * NCOL_ + 8 + fu) * B_ + fb];
        }
        float ig = sigmoid_fast(si + bi);
        float cg = tanh_fast(sc + bc);
        float og = sigmoid_fast(so + bo);
        c_state = fval * c_state + ig * cg;
        float h = og * tanh_fast(c_state);
        g_h[(t + 1) & 1][u_g * B_ + fb] = h;

        if (t == T_ - 1) { out[fb * U_ + u_g] = h; break; }

        // EARLY ARRIVE: publish h before doing any t+1 prefetch, so other CTAs'
        // waits are not gated on this CTA's DRAM reads.
        __syncthreads();   // all h stores in this CTA done
        if (tid == 0) {
            asm volatile("red.release.gpu.global.add.u32 [%0], %1;"
                         :: "l"(&g_bar), "r"(1u) : "memory");
        }

        // Prefetch barrier-independent data for t+1 (overlaps the barrier wait):
        // x chunk 0 (inputs only) + next f value.
        {
            const float* src = xsrc_base + (size_t)(t + 1) * F_;
            #pragma unroll
            for (int j4 = 0; j4 < 8; j4++) {
                float4 v = *(const float4*)(src + j4 * 4);
                int kl = xfq * 32 + j4 * 4;
                st[(kl + 0) * B_ + xb] = v.x; st[(kl + 1) * B_ + xb] = v.y;
                st[(kl + 2) * B_ + xb] = v.z; st[(kl + 3) * B_ + xb] = v.w;
            }
            fval = __ldcg(&g_f_all[(size_t)(t + 1) * (U_ * B_) + u_g * B_ + fb]);
        }

        // WAIT: acquire-poll until all CTAs have arrived for this step.
        if (tid == 0) {
            const unsigned tgt = (unsigned)(t + 1) * GRID_;
            unsigned v;
            do {
                asm volatile("ld.acquire.gpu.global.u32 %0, [%1];"
                             : "=r"(v) : "l"(&g_bar) : "memory");
            } while (v < tgt);
        }
        __syncthreads();
    }
}

extern "C" void kernel_launch(void* const* d_in, const int* in_sizes, int n_in,
                              void* d_out, int out_size) {
    const float* inputs = (const float*)d_in[0];  // [64,1024,256]
    const float* sig    = (const float*)d_in[1];  // [64,1024,31]
    const float* fk     = (const float*)d_in[2];  // [31,512]
    const float* ik     = (const float*)d_in[3];  // [256,1536]
    const float* rk     = (const float*)d_in[4];  // [512,1536]
    const float* bias   = (const float*)d_in[5];  // [2048]
    float* out = (float*)d_out;                   // [64,512]
    (void)in_sizes; (void)n_in; (void)out_size;

    const int smem_bytes = (KTOT_ * NCOL_ * 2 + 2 * KC_ * B_ + KS_ * NCOL_ * B_) * 4;
    cudaFuncSetAttribute(lstm_kernel, cudaFuncAttributeMaxDynamicSharedMemorySize,
                         smem_bytes);

    fpre_kernel<<<T_, THREADS_>>>(sig, fk, bias);
    lstm_kernel<<<GRID_, THREADS_, smem_bytes>>>(inputs, ik, rk, bias, out);
}

// round 3
// speedup vs baseline: 1.1484x; 1.1203x over previous
#include <cuda_runtime.h>
#include <cstdint>
#include <cstddef>

// Problem constants
#define B_      64
#define T_      1024
#define F_      256
#define U_      512
#define G3_     1536
#define SIG_    31

// Persistent kernel config
#define GRID_   128          // CTAs; each owns 4 units
#define THREADS_ 512
#define KTOT_   768          // K = 256 (x) + 512 (h)
#define KC_     128          // K-chunk staged in smem
#define NCH_    6            // chunks per step (2 x, 4 h)
#define NCOL_   12           // 3 gates x 4 units per CTA
#define KSPLIT_ 32           // K-splits across threads (pairs folded by shuffle)
#define JPC_    4            // k values per thread per chunk (128/32)
#define RGRP_   16           // reduction groups after shuffle fold

// Scratch (static __device__ arrays: no allocation)
__device__ float        g_f_all[(size_t)T_ * U_ * B_];   // sigmoid(f_pre), [t][u][b]
__device__ float        g_h[2][U_ * B_];                 // ping-pong h, [k=u][b]
__device__ unsigned int g_bar;

__device__ __forceinline__ void fma2(unsigned long long& a, unsigned long long x,
                                     unsigned long long w) {
    asm("fma.rn.f32x2 %0, %1, %2, %0;" : "+l"(a) : "l"(x), "l"(w));
}
__device__ __forceinline__ float2 up2(unsigned long long v) {
    float2 r; asm("mov.b64 {%0, %1}, %2;" : "=f"(r.x), "=f"(r.y) : "l"(v)); return r;
}
__device__ __forceinline__ float tanh_fast(float x) {
    float y; asm("tanh.approx.f32 %0, %1;" : "=f"(y) : "f"(x)); return y;
}
__device__ __forceinline__ float sigmoid_fast(float x) {
    return 1.f / (1.f + __expf(-x));
}
__device__ __forceinline__ void cp_async16(void* dst_smem, const void* src) {
    unsigned s = (unsigned)__cvta_generic_to_shared(dst_smem);
    asm volatile("cp.async.cg.shared.global [%0], [%1], 16;" :: "r"(s), "l"(src));
}

// f_all[t][u][b] = sigmoid(signatures[b,t,:] . forget_kernel[:,u] + bias_f[u])
// Also resets barrier counter + initial h each launch (graph replays).
__global__ void fpre_kernel(const float* __restrict__ sig, const float* __restrict__ fk,
                            const float* __restrict__ bias) {
    __shared__ float sig_s[B_][33];
    int t = blockIdx.x;
    if (t == 0 && threadIdx.x == 0) g_bar = 0u;
    if (t < GRID_) g_h[0][t * 256 + threadIdx.x] = 0.f;
    for (int i = threadIdx.x; i < B_ * SIG_; i += 256) {
        int b = i / SIG_, d = i - b * SIG_;
        sig_s[b][d] = sig[((size_t)b * T_ + t) * SIG_ + d];
    }
    __syncthreads();
    size_t base = (size_t)t * (U_ * B_);
    for (int idx = threadIdx.x; idx < U_ * B_; idx += 256) {
        int u = idx >> 6, b = idx & 63;
        float acc = bias[U_ + u];
        #pragma unroll
        for (int d = 0; d < SIG_; d++) acc += sig_s[b][d] * __ldg(&fk[d * U_ + u]);
        g_f_all[base + idx] = 1.f / (1.f + expf(-acc));
    }
}

// Persistent recurrence. 512 threads: 16 batch-groups x 32 K-splits, 12 cols each.
// Weights resident in SMEM (dup pairs for f32x2); h staged via cp.async;
// shuffle-fold reduces 32 K-splits to 16 groups before the smem reduction.
__global__ void __launch_bounds__(THREADS_, 1)
lstm_kernel(const float* __restrict__ inputs, const float* __restrict__ ik,
            const float* __restrict__ rk, const float* __restrict__ bias,
            float* __restrict__ out) {
    extern __shared__ float smem[];
    float* w2 = smem;                        // [768][12][2] dup-pair weights  (73728 B)
    float* st = smem + KTOT_ * NCOL_ * 2;    // [2][128][64] stage buffers     (65536 B)
    float* rs = st + 2 * KC_ * B_;           // [16][12][64] reduction         (49152 B)

    const int tid  = threadIdx.x;
    const int ublk = blockIdx.x * 4;

    // Weights: rows 0..255 = input_kernel, 256..767 = recurrent_kernel.
    for (int idx = tid; idx < KTOT_ * NCOL_; idx += THREADS_) {
        int k = idx / NCOL_, j = idx - k * NCOL_;
        int col = (j >> 2) * U_ + ublk + (j & 3);
        float w = (k < F_) ? ik[(size_t)k * G3_ + col]
                           : rk[(size_t)(k - F_) * G3_ + col];
        w2[idx * 2] = w; w2[idx * 2 + 1] = w;
    }

    // GEMM role
    const int b4 = tid & 15;            // batch group (4 batches = 2 f32x2)
    const int ks = tid >> 4;            // 0..31 K-split
    // Finalize role (tid < 256)
    const int fb = tid & 63, fu = (tid >> 6) & 3;
    const int u_g = ublk + fu;
    float bi = 0.f, bc = 0.f, bo = 0.f;
    if (tid < 256) {
        bi = bias[u_g]; bc = bias[2 * U_ + u_g]; bo = bias[3 * U_ + u_g];
    }
    // x transpose-loader roles
    const int lane = tid & 31, wrp = tid >> 5;
    const int xb  = (wrp & 1) * 32 + lane;     // 16-warp role: batch row
    const int xfo = wrp >> 1;                  // 0..7, 16 floats each
    const float* xsrc = inputs + (size_t)xb * T_ * F_ + xfo * 16;
    const int wrp8 = wrp - 8;                  // prefetch role (tid >= 256)
    const int xb2  = ((wrp8 & 1) * 32 + lane) & 63;
    const int xfo2 = (wrp8 >> 1) & 3;          // 0..3, 32 floats each
    const float* xsrc2 = inputs + (size_t)xb2 * T_ * F_ + xfo2 * 32;

    float c_state = 0.f;
    __syncthreads();

    // Pre-load x chunk 0 of t=0 into buffer 0 (transpose [b][f] -> st[f][b])
    {
        #pragma unroll
        for (int j4 = 0; j4 < 4; j4++) {
            float4 v = *(const float4*)(xsrc + j4 * 4);
            int kl = xfo * 16 + j4 * 4;
            st[(kl + 0) * B_ + xb] = v.x; st[(kl + 1) * B_ + xb] = v.y;
            st[(kl + 2) * B_ + xb] = v.z; st[(kl + 3) * B_ + xb] = v.w;
        }
    }
    float fval = (tid < 256) ? __ldcg(&g_f_all[(size_t)u_g * B_ + fb]) : 0.f;

    for (int t = 0; t < T_; t++) {
        unsigned long long acc[NCOL_][2];
        #pragma unroll
        for (int j = 0; j < NCOL_; j++) { acc[j][0] = 0ull; acc[j][1] = 0ull; }

        #pragma unroll
        for (int c = 0; c < NCH_; c++) {
            asm volatile("cp.async.wait_group 0;" ::: "memory");
            __syncthreads();   // stage buffer (c&1) is now published
            if (c == 0) {
                // x chunk 1 -> buffer 1 (register transpose)
                const float* src = xsrc + (size_t)t * F_ + KC_;
                float* d = st + KC_ * B_;
                #pragma unroll
                for (int j4 = 0; j4 < 4; j4++) {
                    float4 v = *(const float4*)(src + j4 * 4);
                    int kl = xfo * 16 + j4 * 4;
                    d[(kl + 0) * B_ + xb] = v.x; d[(kl + 1) * B_ + xb] = v.y;
                    d[(kl + 2) * B_ + xb] = v.z; d[(kl + 3) * B_ + xb] = v.w;
                }
            } else if (c < 5) {
                // h chunk (c+1): async L2 -> smem, no register round-trip
                const float4* src = (const float4*)(g_h[t & 1] + (c - 1) * KC_ * B_);
                float4* dst = (float4*)(st + ((c + 1) & 1) * KC_ * B_);
                #pragma unroll
                for (int r = 0; r < 4; r++)
                    cp_async16(dst + r * THREADS_ + tid, src + r * THREADS_ + tid);
                asm volatile("cp.async.commit_group;" ::: "memory");
            }
            // consume chunk c: 4 k-values per thread, 12 cols
            const float* buf = st + (c & 1) * KC_ * B_;
            const float* wb  = w2 + (size_t)(c * KC_ + ks * JPC_) * (NCOL_ * 2);
            #pragma unroll
            for (int j = 0; j < JPC_; j++) {
                ulonglong2 hv = *(const ulonglong2*)(buf + (ks * JPC_ + j) * B_ + b4 * 4);
                const ulonglong2* wr = (const ulonglong2*)(wb + j * NCOL_ * 2);
                #pragma unroll
                for (int j2 = 0; j2 < 6; j2++) {
                    ulonglong2 wv = wr[j2];
                    fma2(acc[2 * j2    ][0], hv.x, wv.x);
                    fma2(acc[2 * j2    ][1], hv.y, wv.x);
                    fma2(acc[2 * j2 + 1][0], hv.x, wv.y);
                    fma2(acc[2 * j2 + 1][1], hv.y, wv.y);
                }
            }
        }

        // Shuffle-fold ks pairs (lane^16 flips ks bit0), then store 16 groups.
        #pragma unroll
        for (int j = 0; j < NCOL_; j++) {
            #pragma unroll
            for (int p = 0; p < 2; p++) {
                float2 v = up2(acc[j][p]);
                v.x += __shfl_xor_sync(0xffffffffu, v.x, 16);
                v.y += __shfl_xor_sync(0xffffffffu, v.y, 16);
                if ((ks & 1) == 0)
                    *(float2*)&rs[((ks >> 1) * NCOL_ + j) * B_ + b4 * 4 + p * 2] = v;
            }
        }
        __syncthreads();

        if (t == T_ - 1) {
            if (tid < 256) {
                float si = 0.f, sc = 0.f, so = 0.f;
                #pragma unroll
                for (int p = 0; p < RGRP_; p++) {
                    si += rs[(p * NCOL_     + fu) * B_ + fb];
                    sc += rs[(p * NCOL_ + 4 + fu) * B_ + fb];
                    so += rs[(p * NCOL_ + 8 + fu) * B_ + fb];
                }
                float ig = sigmoid_fast(si + bi);
                float cg = tanh_fast(sc + bc);
                float og = sigmoid_fast(so + bo);
                c_state = fval * c_state + ig * cg;
                out[fb * U_ + u_g] = og * tanh_fast(c_state);
            }
            break;
        }

        if (tid < 256) {
            // Finalize gates for this CTA's 4 units x 64 batches
            float si = 0.f, sc = 0.f, so = 0.f;
            #pragma unroll
            for (int p = 0; p < RGRP_; p++) {
                si += rs[(p * NCOL_     + fu) * B_ + fb];
                sc += rs[(p * NCOL_ + 4 + fu) * B_ + fb];
                so += rs[(p * NCOL_ + 8 + fu) * B_ + fb];
            }
            float ig = sigmoid_fast(si + bi);
            float cg = tanh_fast(sc + bc);
            float og = sigmoid_fast(so + bo);
            c_state = fval * c_state + ig * cg;
            float h = og * tanh_fast(c_state);
            g_h[(t + 1) & 1][u_g * B_ + fb] = h;
            // f for t+1 (overlaps barrier wait)
            fval = __ldcg(&g_f_all[(size_t)(t + 1) * (U_ * B_) + u_g * B_ + fb]);
            // Arrive as soon as the finalize half has stored h (named barrier:
            // does NOT wait for the prefetch half's DRAM loads).
            asm volatile("bar.sync 1, 256;" ::: "memory");
            if (tid == 0) {
                asm volatile("red.release.gpu.global.add.u32 [%0], %1;"
                             :: "l"(&g_bar), "r"(1u) : "memory");
                const unsigned tgt = (unsigned)(t + 1) * GRID_;
                unsigned v;
                do {
                    asm volatile("ld.acquire.gpu.global.u32 %0, [%1];"
                                 : "=r"(v) : "l"(&g_bar) : "memory");
                } while (v < tgt);
            }
        } else {
            // Prefetch x chunk 0 of t+1 into buffer 0 (overlaps finalize + wait)
            const float* src = xsrc2 + (size_t)(t + 1) * F_;
            #pragma unroll
            for (int j4 = 0; j4 < 8; j4++) {
                float4 v = *(const float4*)(src + j4 * 4);
                int kl = xfo2 * 32 + j4 * 4;
                st[(kl + 0) * B_ + xb2] = v.x; st[(kl + 1) * B_ + xb2] = v.y;
                st[(kl + 2) * B_ + xb2] = v.z; st[(kl + 3) * B_ + xb2] = v.w;
            }
        }
        __syncthreads();   // barrier passed + buffer 0 ready -> next step
    }
}

extern "C" void kernel_launch(void* const* d_in, const int* in_sizes, int n_in,
                              void* d_out, int out_size) {
    const float* inputs = (const float*)d_in[0];  // [64,1024,256]
    const float* sig    = (const float*)d_in[1];  // [64,1024,31]
    const float* fk     = (const float*)d_in[2];  // [31,512]
    const float* ik     = (const float*)d_in[3];  // [256,1536]
    const float* rk     = (const float*)d_in[4];  // [512,1536]
    const float* bias   = (const float*)d_in[5];  // [2048]
    float* out = (float*)d_out;                   // [64,512]
    (void)in_sizes; (void)n_in; (void)out_size;

    const int smem_bytes = (KTOT_ * NCOL_ * 2 + 2 * KC_ * B_ + RGRP_ * NCOL_ * B_) * 4;
    cudaFuncSetAttribute(lstm_kernel, cudaFuncAttributeMaxDynamicSharedMemorySize,
                         smem_bytes);

    fpre_kernel<<<T_, 256>>>(sig, fk, bias);
    lstm_kernel<<<GRID_, THREADS_, smem_bytes>>>(inputs, ik, rk, bias, out);
}

// round 4
// speedup vs baseline: 1.7065x; 1.4860x over previous
#include <cuda_runtime.h>
#include <cstdint>
#include <cstddef>

// Problem constants
#define B_      64
#define T_      1024
#define F_      256
#define U_      512
#define G3_     1536
#define SIG_    31

// Persistent kernel config
#define GRID_   128          // CTAs; each owns 4 units
#define THREADS_ 512
#define KTOT_   768          // K = 256 (x) + 512 (h)
#define KC_     128          // K-chunk staged in smem
#define NCH_    6            // chunks per step: x0,x1,h0,h1,h2,h3
#define NCOL_   12           // 3 gates x 4 units per CTA
#define JPC_    4            // k values per thread per chunk (128/32 ksplits)
#define RGRP_   16           // reduction groups after shuffle fold
#define CHUNKB_ (KC_ * B_)   // floats per stage buffer (8192 = 32KB)
#define CHW_    (KC_ * NCOL_ * 2)  // weight floats per chunk

// Scratch (static __device__ arrays: no allocation)
__device__ float        g_f_all[(size_t)T_ * U_ * B_];   // sigmoid(f_pre), [t][u][b]
__device__ float        g_x[(size_t)T_ * F_ * B_];       // x transposed, [t][f][b]
__device__ float        g_h[2][U_ * B_];                 // ping-pong h, [u][b]
__device__ unsigned int g_bar;

__device__ __forceinline__ void fma2(unsigned long long& a, unsigned long long x,
                                     unsigned long long w) {
    asm("fma.rn.f32x2 %0, %1, %2, %0;" : "+l"(a) : "l"(x), "l"(w));
}
__device__ __forceinline__ float2 up2(unsigned long long v) {
    float2 r; asm("mov.b64 {%0, %1}, %2;" : "=f"(r.x), "=f"(r.y) : "l"(v)); return r;
}
__device__ __forceinline__ float tanh_fast(float x) {
    float y; asm("tanh.approx.f32 %0, %1;" : "=f"(y) : "f"(x)); return y;
}
__device__ __forceinline__ float sigmoid_fast(float x) {
    return 0.5f * tanh_fast(0.5f * x) + 0.5f;   // 1 MUFU
}
__device__ __forceinline__ void cp_async16(void* dst_smem, const void* src) {
    unsigned s = (unsigned)__cvta_generic_to_shared(dst_smem);
    asm volatile("cp.async.cg.shared.global [%0], [%1], 16;" :: "r"(s), "l"(src));
}
#define CP_COMMIT() asm volatile("cp.async.commit_group;" ::: "memory")
#define CP_WAIT(n)  asm volatile("cp.async.wait_group %0;" :: "n"(n) : "memory")

// fpre: f_all[t][u][b] = sigmoid(sig[b,t,:] . fk[:,u] + b_f[u]); also transposes
// x into g_x[t][f][b] and resets barrier counter + initial h (graph replays).
__global__ void fpre_kernel(const float* __restrict__ inputs,
                            const float* __restrict__ sig,
                            const float* __restrict__ fk,
                            const float* __restrict__ bias) {
    extern __shared__ float xs[];            // [256][65] transpose tile (66560 B)
    __shared__ float sig_s[B_][33];
    const int t = blockIdx.x, tid = threadIdx.x;
    if (t == 0 && tid == 0) g_bar = 0u;
    if (t < GRID_) g_h[0][t * 256 + tid] = 0.f;

    // x transpose tile: read [b][f] coalesced, write xs[f][b] (stride 65: no conflicts)
    for (int i = tid; i < B_ * F_; i += 256) {
        int b = i >> 8, f = i & 255;
        xs[f * 65 + b] = inputs[((size_t)b * T_ + t) * F_ + f];
    }
    for (int i = tid; i < B_ * SIG_; i += 256) {
        int b = i / SIG_, d = i - b * SIG_;
        sig_s[b][d] = sig[((size_t)b * T_ + t) * SIG_ + d];
    }
    __syncthreads();
    for (int j = tid; j < F_ * B_; j += 256) {
        int f = j >> 6, b = j & 63;
        g_x[(size_t)t * (F_ * B_) + j] = xs[f * 65 + b];
    }
    size_t base = (size_t)t * (U_ * B_);
    for (int idx = tid; idx < U_ * B_; idx += 256) {
        int u = idx >> 6, b = idx & 63;
        float acc = bias[U_ + u];
        #pragma unroll
        for (int d = 0; d < SIG_; d++) acc += sig_s[b][d] * __ldg(&fk[d * U_ + u]);
        g_f_all[base + idx] = 1.f / (1.f + expf(-acc));
    }
}

// Persistent recurrence. 512 threads: 16 batch-groups x 32 K-splits, 12 cols each.
// 3-buffer cp.async ring, issue-ahead-by-2; grid-barrier poll overlapped with the
// h-independent x0 chunk; weights resident in SMEM as dup pairs for f32x2 FMA.
__global__ void __launch_bounds__(THREADS_, 1)
lstm_kernel(const float* __restrict__ ik, const float* __restrict__ rk,
            const float* __restrict__ bias, float* __restrict__ out) {
    extern __shared__ float smem[];
    float* w2 = smem;                        // [768][12][2] dup-pair weights (73728 B)
    float* st = smem + KTOT_ * NCOL_ * 2;    // 3 x [128][64] ring buffers    (98304 B)
    float* rs = st + 3 * CHUNKB_;            // [16][12][64] reduction        (49152 B)

    const int tid  = threadIdx.x;
    const int ublk = blockIdx.x * 4;

    // Weights: rows 0..255 = input_kernel, 256..767 = recurrent_kernel.
    for (int idx = tid; idx < KTOT_ * NCOL_; idx += THREADS_) {
        int k = idx / NCOL_, j = idx - k * NCOL_;
        int col = (j >> 2) * U_ + ublk + (j & 3);
        float w = (k < F_) ? ik[(size_t)k * G3_ + col]
                           : rk[(size_t)(k - F_) * G3_ + col];
        w2[idx * 2] = w; w2[idx * 2 + 1] = w;
    }

    const int b4 = tid & 15;            // batch group (4 batches = 2 f32x2)
    const int ks = tid >> 4;            // 0..31 K-split
    const int fb = tid & 63, fu = (tid >> 6) & 3;
    const int u_g = ublk + fu;
    float bi = 0.f, bc = 0.f, bo = 0.f;
    if (tid < 256) {
        bi = bias[u_g]; bc = bias[2 * U_ + u_g]; bo = bias[3 * U_ + u_g];
    }

    float c_state = 0.f;
    float fval = (tid < 256) ? __ldcg(&g_f_all[(size_t)u_g * B_ + fb]) : 0.f;
    __syncthreads();   // weights ready

    // Prologue: issue x0(0) -> buf0, x1(0) -> buf1 (pending groups = 2)
    {
        const float4* s0 = (const float4*)(g_x);
        const float4* s1 = (const float4*)(g_x + CHUNKB_);
        float4* d0 = (float4*)st;
        float4* d1 = (float4*)(st + CHUNKB_);
        #pragma unroll
        for (int r = 0; r < 4; r++) cp_async16(d0 + r * THREADS_ + tid, s0 + r * THREADS_ + tid);
        CP_COMMIT();
        #pragma unroll
        for (int r = 0; r < 4; r++) cp_async16(d1 + r * THREADS_ + tid, s1 + r * THREADS_ + tid);
        CP_COMMIT();
    }

    for (int t = 0; t < T_; t++) {
        unsigned long long acc[NCOL_][2];
        #pragma unroll
        for (int j = 0; j < NCOL_; j++) { acc[j][0] = 0ull; acc[j][1] = 0ull; }

        const float* hsrc = g_h[t & 1];
        const int tn = (t + 1 < T_) ? t + 1 : 0;   // bounds-safe prefetch index

        #pragma unroll
        for (int c = 0; c < NCH_; c++) {
            if (c == 1) { CP_WAIT(0); } else { CP_WAIT(1); }
            __syncthreads();
            if (c == 0) {
                // poll grid barrier while the other warps chew on x0
                if (tid == 0 && t > 0) {
                    const unsigned tgt = (unsigned)t * GRID_;
                    unsigned v;
                    do {
                        asm volatile("ld.acquire.gpu.global.u32 %0, [%1];"
                                     : "=r"(v) : "l"(&g_bar) : "memory");
                    } while (v < tgt);
                }
            } else {
                // issue chunk c+1 (0-based chunk c issues chunk c+... ahead-by-2
                // schedule: at phase c we issue chunk c+2's data; for c==1 we issue
                // BOTH h0 and h1 (h was not ready before the barrier).
                if (c == 1) {
                    const float4* s0 = (const float4*)(hsrc);
                    const float4* s1 = (const float4*)(hsrc + CHUNKB_);
                    float4* d0 = (float4*)(st + 2 * CHUNKB_);  // buf2
                    float4* d1 = (float4*)(st);                // buf0
                    #pragma unroll
                    for (int r = 0; r < 4; r++) cp_async16(d0 + r * THREADS_ + tid, s0 + r * THREADS_ + tid);
                    CP_COMMIT();
                    #pragma unroll
                    for (int r = 0; r < 4; r++) cp_async16(d1 + r * THREADS_ + tid, s1 + r * THREADS_ + tid);
                    CP_COMMIT();
                } else {
                    const float4* s;
                    if (c == 2)      s = (const float4*)(hsrc + 2 * CHUNKB_);  // h2
                    else if (c == 3) s = (const float4*)(hsrc + 3 * CHUNKB_);  // h3
                    else if (c == 4) s = (const float4*)(g_x + (size_t)tn * (F_ * B_)); // x0'
                    else             s = (const float4*)(g_x + (size_t)tn * (F_ * B_) + CHUNKB_); // x1'
                    float4* d = (float4*)(st + ((c + 2) % 3) * CHUNKB_);
                    #pragma unroll
                    for (int r = 0; r < 4; r++) cp_async16(d + r * THREADS_ + tid, s + r * THREADS_ + tid);
                    CP_COMMIT();
                }
            }
            // consume chunk c from buf (c % 3)
            const float* buf = st + (c % 3) * CHUNKB_;
            const float* wb  = w2 + c * CHW_ + (ks * JPC_) * (NCOL_ * 2);
            #pragma unroll
            for (int j = 0; j < JPC_; j++) {
                ulonglong2 hv = *(const ulonglong2*)(buf + (ks * JPC_ + j) * B_ + b4 * 4);
                const ulonglong2* wr = (const ulonglong2*)(wb + j * NCOL_ * 2);
                #pragma unroll
                for (int j2 = 0; j2 < 6; j2++) {
                    ulonglong2 wv = wr[j2];
                    fma2(acc[2 * j2    ][0], hv.x, wv.x);
                    fma2(acc[2 * j2    ][1], hv.y, wv.x);
                    fma2(acc[2 * j2 + 1][0], hv.x, wv.y);
                    fma2(acc[2 * j2 + 1][1], hv.y, wv.y);
                }
            }
        }

        // Shuffle-fold ks pairs (lane^16), store 16 reduction groups.
        #pragma unroll
        for (int j = 0; j < NCOL_; j++) {
            #pragma unroll
            for (int p = 0; p < 2; p++) {
                float2 v = up2(acc[j][p]);
                v.x += __shfl_xor_sync(0xffffffffu, v.x, 16);
                v.y += __shfl_xor_sync(0xffffffffu, v.y, 16);
                if ((ks & 1) == 0)
                    *(float2*)&rs[((ks >> 1) * NCOL_ + j) * B_ + b4 * 4 + p * 2] = v;
            }
        }
        __syncthreads();

        if (tid < 256) {
            float si = 0.f, sc = 0.f, so = 0.f;
            #pragma unroll
            for (int p = 0; p < RGRP_; p++) {
                si += rs[(p * NCOL_     + fu) * B_ + fb];
                sc += rs[(p * NCOL_ + 4 + fu) * B_ + fb];
                so += rs[(p * NCOL_ + 8 + fu) * B_ + fb];
            }
            float ig = sigmoid_fast(si + bi);
            float cg = tanh_fast(sc + bc);
            float og = sigmoid_fast(so + bo);
            c_state = fval * c_state + ig * cg;
            float h = og * tanh_fast(c_state);
            if (t == T_ - 1) {
                out[fb * U_ + u_g] = h;
            } else {
                g_h[(t + 1) & 1][u_g * B_ + fb] = h;
                asm volatile("bar.sync 1, 256;" ::: "memory");   // finalize half only
                if (tid == 0) {
                    asm volatile("red.release.gpu.global.add.u32 [%0], %1;"
                                 :: "l"(&g_bar), "r"(1u) : "memory");
                }
                fval = __ldcg(&g_f_all[(size_t)(t + 1) * (U_ * B_) + u_g * B_ + fb]);
            }
        }
        // no trailing sync: next phase 0 starts with wait_group + syncthreads
    }
    CP_WAIT(0);   // drain pending prefetches before exit
}

extern "C" void kernel_launch(void* const* d_in, const int* in_sizes, int n_in,
                              void* d_out, int out_size) {
    const float* inputs = (const float*)d_in[0];  // [64,1024,256]
    const float* sig    = (const float*)d_in[1];  // [64,1024,31]
    const float* fk     = (const float*)d_in[2];  // [31,512]
    const float* ik     = (const float*)d_in[3];  // [256,1536]
    const float* rk     = (const float*)d_in[4];  // [512,1536]
    const float* bias   = (const float*)d_in[5];  // [2048]
    float* out = (float*)d_out;                   // [64,512]
    (void)in_sizes; (void)n_in; (void)out_size;

    const int fpre_smem = 256 * 65 * 4;  // 66560 B transpose tile
    cudaFuncSetAttribute(fpre_kernel, cudaFuncAttributeMaxDynamicSharedMemorySize,
                         fpre_smem);
    const int smem_bytes = (KTOT_ * NCOL_ * 2 + 3 * CHUNKB_ + RGRP_ * NCOL_ * B_) * 4;
    cudaFuncSetAttribute(lstm_kernel, cudaFuncAttributeMaxDynamicSharedMemorySize,
                         smem_bytes);

    fpre_kernel<<<T_, 256, fpre_smem>>>(inputs, sig, fk, bias);
    lstm_kernel<<<GRID_, THREADS_, smem_bytes>>>(ik, rk, bias, out);
}